// round 6
// baseline (speedup 1.0000x reference)
#include <cuda_runtime.h>
#include <cuda_bf16.h>
#include <cstdint>

#define B 8
#define N 65536
#define C 256
#define NS 1024
#define K1 259              // real K of layer 1 (3 xyz + 256 feat)
#define KP 272              // padded K (multiple of 16)
#define M 128
#define MH 64               // M per block
#define NT 64
#define KT 16
#define EPS 1e-5f
#define PPT 64              // points per thread in ballquery

// ---------------- scratch (device globals; no allocs) ---------------------
__device__ __align__(256) int      d_inds[B][NS];
__device__ __align__(256) float    d_gxyz[B][3][NS];
__device__ __align__(256) float    d_y1[B][M][NS];
__device__ __align__(256) float    d_y2[B][M][NS];
__device__ __align__(256) float    d_wT1[KP][M];
__device__ __align__(256) float    d_wT2[M][M];
__device__ __align__(256) float    d_wT3[M][M];
__device__ __align__(256) float    d_sum [3][M];
__device__ __align__(256) float    d_sum2[3][M];
__device__ __align__(256) unsigned d_maxenc[B][M];
__device__ __align__(256) unsigned d_minenc[B][M];

template<int L> __device__ __forceinline__ const float* layer_in();
template<> __device__ __forceinline__ const float* layer_in<1>() { return &d_y1[0][0][0]; }
template<> __device__ __forceinline__ const float* layer_in<2>() { return &d_y2[0][0][0]; }
template<int L> __device__ __forceinline__ float* layer_out();
template<> __device__ __forceinline__ float* layer_out<0>() { return &d_y1[0][0][0]; }
template<> __device__ __forceinline__ float* layer_out<1>() { return &d_y2[0][0][0]; }
template<int L> __device__ __forceinline__ const float* wT();
template<> __device__ __forceinline__ const float* wT<0>() { return &d_wT1[0][0]; }
template<> __device__ __forceinline__ const float* wT<1>() { return &d_wT2[0][0]; }
template<> __device__ __forceinline__ const float* wT<2>() { return &d_wT3[0][0]; }

__device__ __forceinline__ unsigned enc(float f) {
    unsigned u = __float_as_uint(f);
    return (u & 0x80000000u) ? ~u : (u | 0x80000000u);
}
__device__ __forceinline__ float dec(unsigned u) {
    return __uint_as_float((u & 0x80000000u) ? (u ^ 0x80000000u) : ~u);
}

// ---------- 0) setup: blocks 0-7 ballquery (parallel 2-pass), 8-23 prep ----
__global__ void __launch_bounds__(1024)
setup_kernel(const float* __restrict__ xyz,
             const float* __restrict__ w1,
             const float* __restrict__ w2,
             const float* __restrict__ w3) {
    int blk = blockIdx.x;
    int tid = threadIdx.x;

    if (blk >= B) {
        // ---- prep: transpose weights, zero accumulators ----
        int gtid = (blk - B) * 1024 + tid;
        int nthr = 16 * 1024;
        for (int i = gtid; i < 3 * M; i += nthr) { (&d_sum[0][0])[i] = 0.f; (&d_sum2[0][0])[i] = 0.f; }
        for (int i = gtid; i < B * M; i += nthr) { (&d_maxenc[0][0])[i] = 0u; (&d_minenc[0][0])[i] = 0xFFFFFFFFu; }
        for (int i = gtid; i < KP * M; i += nthr) {
            int k = i / M, m = i % M;
            d_wT1[k][m] = (k < K1) ? w1[m * K1 + k] : 0.f;
        }
        for (int i = gtid; i < M * M; i += nthr) {
            int k = i / M, m = i % M;
            d_wT2[k][m] = w2[m * M + k];
            d_wT3[k][m] = w3[m * M + k];
        }
        return;
    }

    // ---- ballquery for batch b = blk ----
    int b = blk;
    const float* x = xyz + (size_t)b * N * 3;
    float cx = x[0], cy = x[1], cz = x[2];
    int lane = tid & 31, warp = tid >> 5;

    // pass 1: each thread owns 64 contiguous points; build validity mask
    unsigned long long mask = 0ull;
    int cnt = 0;
    const float* base = x + (size_t)tid * PPT * 3;
    #pragma unroll 8
    for (int i = 0; i < PPT; i++) {
        float dx = base[i*3+0] - cx;
        float dy = base[i*3+1] - cy;
        float dz = base[i*3+2] - cz;
        if (dx*dx + dy*dy + dz*dz < 1.0f) { mask |= (1ull << i); cnt++; }
    }

    // block-wide scan of per-thread counts
    __shared__ int wsum[32];
    int incl = cnt;
    #pragma unroll
    for (int o = 1; o < 32; o <<= 1) {
        int t2 = __shfl_up_sync(0xffffffffu, incl, o);
        if (lane >= o) incl += t2;
    }
    if (lane == 31) wsum[warp] = incl;
    __syncthreads();
    if (tid < 32) {
        int v = wsum[tid];
        #pragma unroll
        for (int o = 1; o < 32; o <<= 1) {
            int t2 = __shfl_up_sync(0xffffffffu, v, o);
            if (tid >= o) v += t2;
        }
        wsum[tid] = v;               // inclusive over warps
    }
    __syncthreads();
    int excl = incl - cnt + (warp ? wsum[warp - 1] : 0);
    int total = wsum[31];

    // pass 2: emit indices at prefix positions (ascending order guaranteed)
    if (excl < NS) {
        int pos = excl;
        unsigned long long m = mask;
        while (m && pos < NS) {
            int i = __ffsll((long long)m) - 1;
            d_inds[b][pos++] = tid * PPT + i;
            m &= (m - 1);
        }
    }
    // tail fill: first valid index is always 0 (center point, d2 == 0)
    for (int p = min(total, NS) + tid; p < NS; p += 1024) d_inds[b][p] = 0;
    __syncthreads();

    // relative xyz rows
    for (int n = tid; n < NS; n += 1024) {
        int id = d_inds[b][n];
        d_gxyz[b][0][n] = x[id*3+0] - cx;
        d_gxyz[b][1][n] = x[id*3+1] - cy;
        d_gxyz[b][2][n] = x[id*3+2] - cz;
    }
}

// ---------------- fused (gather+)GEMM + BN-prev + stats(+max) -------------
template<int K, int LAYER>
__global__ void __launch_bounds__(256)
gemm_kernel(const float* __restrict__ feat,
            const float* __restrict__ bias,
            const float* __restrict__ gamma_prev,
            const float* __restrict__ beta_prev) {
    __shared__ float As[KT][MH];
    __shared__ float Bs[KT][NT];
    __shared__ float red [16][MH + 1];
    __shared__ float red2[16][MH + 1];
    __shared__ float s_scale[M], s_shift[M];
    __shared__ int   s_inds[NT];

    int n0 = blockIdx.x * NT;
    int m0 = blockIdx.y * MH;
    int b  = blockIdx.z;
    int tid = threadIdx.x;               // 256
    int tm = (tid & 15) * 4;
    int tn = (tid >> 4) * 4;
    int g  = tid >> 4;

    if (LAYER == 0) {
        if (tid < NT) s_inds[tid] = d_inds[b][n0 + tid];
    } else {
        if (tid < M) {
            float inv = 1.0f / (float)(B * NS);
            float mn  = d_sum [LAYER-1][tid] * inv;
            float var = d_sum2[LAYER-1][tid] * inv - mn * mn;
            float a = gamma_prev[tid] * rsqrtf(var + EPS);
            s_scale[tid] = a;
            s_shift[tid] = beta_prev[tid] - mn * a;
        }
    }
    __syncthreads();

    float acc[4][4] = {};
    const float* Wt = wT<LAYER>();
    const float* fb = feat + (size_t)b * C * N;
    const float* Xb = (LAYER > 0) ? layer_in<(LAYER > 0 ? LAYER : 1)>() + (size_t)b * M * NS : nullptr;

    int bkk = tid >> 4;                  // load row (0..15)
    int bn4 = (tid & 15) * 4;            // load col base

    float4 ra, rb;
    // prefetch k0 = 0
    {
        ra = *(const float4*)&Wt[bkk * M + m0 + bn4];
        int row = bkk;
        if (LAYER == 0) {
            if (row < 3) rb = *(const float4*)&d_gxyz[b][row][n0 + bn4];
            else {
                const float* fr = fb + (size_t)(row - 3) * N;
                rb.x = __ldg(fr + s_inds[bn4 + 0]);
                rb.y = __ldg(fr + s_inds[bn4 + 1]);
                rb.z = __ldg(fr + s_inds[bn4 + 2]);
                rb.w = __ldg(fr + s_inds[bn4 + 3]);
            }
        } else {
            rb = *(const float4*)&Xb[(size_t)row * NS + n0 + bn4];
        }
    }

    for (int k0 = 0; k0 < K; k0 += KT) {
        // commit prefetched tile (apply BN to B now, from smem scale/shift)
        *(float4*)&As[bkk][bn4] = ra;
        if (LAYER > 0) {
            float a = s_scale[k0 + bkk], h = s_shift[k0 + bkk];
            rb.x = fmaxf(fmaf(a, rb.x, h), 0.f);
            rb.y = fmaxf(fmaf(a, rb.y, h), 0.f);
            rb.z = fmaxf(fmaf(a, rb.z, h), 0.f);
            rb.w = fmaxf(fmaf(a, rb.w, h), 0.f);
        }
        *(float4*)&Bs[bkk][bn4] = rb;
        __syncthreads();

        // prefetch next tile while computing this one
        if (k0 + KT < K) {
            int kn = k0 + KT;
            ra = *(const float4*)&Wt[(kn + bkk) * M + m0 + bn4];
            int row = kn + bkk;
            if (LAYER == 0) {
                if (row < 3) rb = *(const float4*)&d_gxyz[b][row][n0 + bn4];
                else if (row < K1) {
                    const float* fr = fb + (size_t)(row - 3) * N;
                    rb.x = __ldg(fr + s_inds[bn4 + 0]);
                    rb.y = __ldg(fr + s_inds[bn4 + 1]);
                    rb.z = __ldg(fr + s_inds[bn4 + 2]);
                    rb.w = __ldg(fr + s_inds[bn4 + 3]);
                } else {
                    rb = make_float4(0.f, 0.f, 0.f, 0.f);
                }
            } else {
                rb = *(const float4*)&Xb[(size_t)row * NS + n0 + bn4];
            }
        }

        #pragma unroll
        for (int kk = 0; kk < KT; kk++) {
            float4 a0 = *(float4*)&As[kk][tm];
            float4 bb = *(float4*)&Bs[kk][tn];
            float av[4] = {a0.x, a0.y, a0.z, a0.w};
            float bv[4] = {bb.x, bb.y, bb.z, bb.w};
            #pragma unroll
            for (int i = 0; i < 4; i++)
                #pragma unroll
                for (int j = 0; j < 4; j++)
                    acc[i][j] = fmaf(av[i], bv[j], acc[i][j]);
        }
        __syncthreads();
    }

    // ---- epilogue: bias, optional store, channel stats, optional extrema --
    float* Yb = (LAYER < 2) ? layer_out<(LAYER < 2 ? LAYER : 0)>() + (size_t)b * M * NS : nullptr;
    float rmax[4], rmin[4];
    #pragma unroll
    for (int i = 0; i < 4; i++) {
        float bi = bias[m0 + tm + i];
        float s = 0.f, s2 = 0.f, mx = -3.0e38f, mnv = 3.0e38f;
        #pragma unroll
        for (int j = 0; j < 4; j++) {
            float v = acc[i][j] + bi;
            acc[i][j] = v;
            s += v; s2 += v * v;
            mx = fmaxf(mx, v); mnv = fminf(mnv, v);
        }
        if (LAYER < 2)
            *(float4*)&Yb[(size_t)(m0 + tm + i) * NS + n0 + tn] =
                make_float4(acc[i][0], acc[i][1], acc[i][2], acc[i][3]);
        red [g][tm + i] = s;
        red2[g][tm + i] = s2;
        rmax[i] = mx; rmin[i] = mnv;
    }
    __syncthreads();
    if (tid < MH) {
        float s = 0.f, s2 = 0.f;
        #pragma unroll
        for (int gg = 0; gg < 16; gg++) { s += red[gg][tid]; s2 += red2[gg][tid]; }
        atomicAdd(&d_sum [LAYER][m0 + tid], s);
        atomicAdd(&d_sum2[LAYER][m0 + tid], s2);
    }
    if (LAYER == 2) {
        __syncthreads();
        #pragma unroll
        for (int i = 0; i < 4; i++) { red[g][tm + i] = rmax[i]; red2[g][tm + i] = rmin[i]; }
        __syncthreads();
        if (tid < MH) {
            float mx = -3.0e38f, mnv = 3.0e38f;
            #pragma unroll
            for (int gg = 0; gg < 16; gg++) { mx = fmaxf(mx, red[gg][tid]); mnv = fminf(mnv, red2[gg][tid]); }
            atomicMax(&d_maxenc[b][m0 + tid], enc(mx));
            atomicMin(&d_minenc[b][m0 + tid], enc(mnv));
        }
    }
}

// ---------------- FC head (single block) ----------------------------------
__global__ void head_kernel(const float* __restrict__ xyz,
                            const float* __restrict__ g3,  const float* __restrict__ be3,
                            const float* __restrict__ hw1, const float* __restrict__ hb1,
                            const float* __restrict__ hg1, const float* __restrict__ hbe1,
                            const float* __restrict__ hw2, const float* __restrict__ hb2,
                            const float* __restrict__ hg2, const float* __restrict__ hbe2,
                            const float* __restrict__ hw3, const float* __restrict__ hb3,
                            float* __restrict__ out) {
    __shared__ float sf[B][M];
    __shared__ float z [B][M];
    __shared__ float sa[M], sb_[M];
    int tid = threadIdx.x;          // 1024
    int b = tid >> 7, o = tid & 127;

    if (tid < M) {
        float inv = 1.0f / (float)(B * NS);
        float mn  = d_sum [2][tid] * inv;
        float var = d_sum2[2][tid] * inv - mn * mn;
        float a = g3[tid] * rsqrtf(var + EPS);
        sa[tid] = a;
        sb_[tid] = be3[tid] - mn * a;
    }
    __syncthreads();
    {
        float a = sa[o], d = sb_[o];
        float mx = dec(d_maxenc[b][o]);
        float mnv = dec(d_minenc[b][o]);
        float v = (a >= 0.f) ? fmaf(a, mx, d) : fmaf(a, mnv, d);
        sf[b][o] = fmaxf(v, 0.f);
    }
    __syncthreads();

    // layer 1
    {
        float acc = hb1[o];
        #pragma unroll 8
        for (int k = 0; k < M; k++) acc = fmaf(sf[b][k], hw1[o * M + k], acc);
        z[b][o] = acc;
    }
    __syncthreads();
    if (tid < M) {
        float s = 0.f, s2 = 0.f;
        for (int bb = 0; bb < B; bb++) { float v = z[bb][tid]; s += v; s2 += v * v; }
        float mn = s * 0.125f, var = s2 * 0.125f - mn * mn;
        float a = hg1[tid] * rsqrtf(var + EPS);
        sa[tid] = a; sb_[tid] = hbe1[tid] - mn * a;
    }
    __syncthreads();
    sf[b][o] = fmaxf(fmaf(sa[o], z[b][o], sb_[o]), 0.f);
    __syncthreads();

    // layer 2
    {
        float acc = hb2[o];
        #pragma unroll 8
        for (int k = 0; k < M; k++) acc = fmaf(sf[b][k], hw2[o * M + k], acc);
        z[b][o] = acc;
    }
    __syncthreads();
    if (tid < M) {
        float s = 0.f, s2 = 0.f;
        for (int bb = 0; bb < B; bb++) { float v = z[bb][tid]; s += v; s2 += v * v; }
        float mn = s * 0.125f, var = s2 * 0.125f - mn * mn;
        float a = hg2[tid] * rsqrtf(var + EPS);
        sa[tid] = a; sb_[tid] = hbe2[tid] - mn * a;
    }
    __syncthreads();
    sf[b][o] = fmaxf(fmaf(sa[o], z[b][o], sb_[o]), 0.f);
    __syncthreads();

    // layer 3
    if (tid < B * 12) {
        int bb = tid / 12, oo = tid % 12;
        float acc = hb3[oo];
        #pragma unroll 8
        for (int k = 0; k < M; k++) acc = fmaf(sf[bb][k], hw3[oo * M + k], acc);
        if (oo < 3)      out[bb * 3 + oo]            = xyz[(size_t)bb * N * 3 + oo] + acc;
        else if (oo < 6) out[24 + bb * 3 + (oo - 3)] = acc;
        else             out[48 + bb * 6 + (oo - 6)] = acc;
    }
}

// ---------------- launch ---------------------------------------------------
extern "C" void kernel_launch(void* const* d_in, const int* in_sizes, int n_in,
                              void* d_out, int out_size) {
    const float* xyz  = (const float*)d_in[0];
    const float* feat = (const float*)d_in[1];
    const float* w1   = (const float*)d_in[2];
    const float* b1   = (const float*)d_in[3];
    const float* g1   = (const float*)d_in[4];
    const float* be1  = (const float*)d_in[5];
    const float* w2   = (const float*)d_in[6];
    const float* b2   = (const float*)d_in[7];
    const float* g2   = (const float*)d_in[8];
    const float* be2  = (const float*)d_in[9];
    const float* w3   = (const float*)d_in[10];
    const float* b3   = (const float*)d_in[11];
    const float* g3   = (const float*)d_in[12];
    const float* be3  = (const float*)d_in[13];
    const float* hw1  = (const float*)d_in[14];
    const float* hb1  = (const float*)d_in[15];
    const float* hg1  = (const float*)d_in[16];
    const float* hbe1 = (const float*)d_in[17];
    const float* hw2  = (const float*)d_in[18];
    const float* hb2  = (const float*)d_in[19];
    const float* hg2  = (const float*)d_in[20];
    const float* hbe2 = (const float*)d_in[21];
    const float* hw3  = (const float*)d_in[22];
    const float* hb3  = (const float*)d_in[23];
    float* out = (float*)d_out;

    setup_kernel<<<B + 16, 1024>>>(xyz, w1, w2, w3);

    dim3 gemm_grid(NS / NT, M / MH, B);      // (16, 2, 8) = 256 blocks
    gemm_kernel<KP, 0><<<gemm_grid, 256>>>(feat, b1, nullptr, nullptr);
    gemm_kernel<M,  1><<<gemm_grid, 256>>>(feat, b2, g1, be1);
    gemm_kernel<M,  2><<<gemm_grid, 256>>>(feat, b3, g2, be2);

    head_kernel<<<1, 1024>>>(xyz, g3, be3,
                             hw1, hb1, hg1, hbe1,
                             hw2, hb2, hg2, hbe2, hw3, hb3, out);
}